// round 1
// baseline (speedup 1.0000x reference)
#include <cuda_runtime.h>

#define NG   2048
#define NB   4
#define CIN  16
#define COUT 32
#define NCTX 256
#define NOUT 1024

#define TPB  256
#define TGT_PER_WARP 4
#define TGT_PER_BLOCK (8 * TGT_PER_WARP)   // 8 warps * 4 targets = 32

__device__ float g_xmin;
__device__ float g_step;
__device__ float g_k[CIN];      // -0.5/s_c^2 * log2(e)
__device__ int   g_uniform;

__device__ __forceinline__ float ex2(float x) {
    float y;
    asm("ex2.approx.ftz.f32 %0, %1;" : "=f"(y) : "f"(x));
    return y;
}

// ---------------------------------------------------------------------------
// Prep: global min/max over x_context and x_target, per-channel exponent coeffs,
// runtime uniformity check (correct for arbitrary sigma).
// ---------------------------------------------------------------------------
__global__ void prep_kernel(const float* __restrict__ xc,
                            const float* __restrict__ xt,
                            const float* __restrict__ sigma) {
    __shared__ float smin[TPB];
    __shared__ float smax[TPB];
    __shared__ float sk[CIN];
    int tid = threadIdx.x;

    float mn = 1e30f, mx = -1e30f;
    for (int i = tid; i < NB * NCTX; i += TPB) {
        float v = xc[i];
        mn = fminf(mn, v); mx = fmaxf(mx, v);
    }
    for (int i = tid; i < NB * NOUT; i += TPB) {
        float v = xt[i];
        mn = fminf(mn, v); mx = fmaxf(mx, v);
    }
    smin[tid] = mn; smax[tid] = mx;

    if (tid < CIN) {
        float s = expf(sigma[tid]);
        sk[tid] = (-0.5f / (s * s)) * 1.4426950408889634f;
    }
    __syncthreads();

    for (int s = TPB / 2; s > 0; s >>= 1) {
        if (tid < s) {
            smin[tid] = fminf(smin[tid], smin[tid + s]);
            smax[tid] = fmaxf(smax[tid], smax[tid + s]);
        }
        __syncthreads();
    }

    if (tid == 0) {
        float xmin = smin[0] - 0.1f;
        float xmax = smax[0] + 0.1f;
        g_xmin = xmin;
        g_step = (xmax - xmin) / (float)(NG - 1);
        int u = 1;
        #pragma unroll
        for (int c = 1; c < CIN; c++) u &= (sk[c] == sk[0]) ? 1 : 0;
        g_uniform = u;
    }
    if (tid < CIN) g_k[tid] = sk[tid];
}

// ---------------------------------------------------------------------------
// Main: block = (batch, 32-target tile). r[b] staged in SMEM (c-major,
// conflict-free scalar LDS). Warp owns 4 targets; lanes stride over grid.
// Fused epilogue: butterfly-reduce 4x16 accumulators, lane = output channel.
// ---------------------------------------------------------------------------
extern __shared__ float s_buf[];

__global__ __launch_bounds__(TPB, 1)
void conv_decoder_kernel(const float* __restrict__ r,
                         const float* __restrict__ xt,
                         const float* __restrict__ W,
                         const float* __restrict__ bias,
                         float* __restrict__ out) {
    float* r_s = s_buf;                 // CIN * NG
    float* W_s = s_buf + CIN * NG;      // CIN * COUT
    float* b_s = W_s + CIN * COUT;      // COUT

    const int b    = blockIdx.y;
    const int tid  = threadIdx.x;
    const int warp = tid >> 5;
    const int lane = tid & 31;

    // Stage r[b] (128 KB) into smem, vectorized & coalesced.
    {
        const float4* src = (const float4*)(r + (size_t)b * CIN * NG);
        float4* dst = (float4*)r_s;
        #pragma unroll
        for (int i = tid; i < CIN * NG / 4; i += TPB) dst[i] = src[i];
    }
    for (int i = tid; i < CIN * COUT; i += TPB) W_s[i] = W[i];
    if (tid < COUT) b_s[tid] = bias[tid];
    __syncthreads();

    const float xmin = g_xmin;
    const float step = g_step;
    const int o0 = blockIdx.x * TGT_PER_BLOCK + warp * TGT_PER_WARP;

    float xtv[TGT_PER_WARP];
    #pragma unroll
    for (int t = 0; t < TGT_PER_WARP; t++) xtv[t] = xt[b * NOUT + o0 + t];

    float acc[TGT_PER_WARP][CIN];
    #pragma unroll
    for (int t = 0; t < TGT_PER_WARP; t++)
        #pragma unroll
        for (int c = 0; c < CIN; c++) acc[t][c] = 0.0f;

    if (g_uniform) {
        // One EX2 per (target, grid-point); weight shared across 16 channels.
        const float k0 = g_k[0];
        for (int i = lane; i < NG; i += 32) {
            float gv = fmaf((float)i, step, xmin);
            float rc[CIN];
            #pragma unroll
            for (int c = 0; c < CIN; c++) rc[c] = r_s[c * NG + i];
            #pragma unroll
            for (int t = 0; t < TGT_PER_WARP; t++) {
                float d = gv - xtv[t];
                float w = ex2(d * d * k0);
                #pragma unroll
                for (int c = 0; c < CIN; c++)
                    acc[t][c] = fmaf(rc[c], w, acc[t][c]);
            }
        }
    } else {
        // General path: per-channel length scales.
        float kk[CIN];
        #pragma unroll
        for (int c = 0; c < CIN; c++) kk[c] = g_k[c];
        for (int i = lane; i < NG; i += 32) {
            float gv = fmaf((float)i, step, xmin);
            float rc[CIN];
            #pragma unroll
            for (int c = 0; c < CIN; c++) rc[c] = r_s[c * NG + i];
            #pragma unroll
            for (int t = 0; t < TGT_PER_WARP; t++) {
                float d = gv - xtv[t];
                float d2 = d * d;
                #pragma unroll
                for (int c = 0; c < CIN; c++)
                    acc[t][c] = fmaf(rc[c], ex2(d2 * kk[c]), acc[t][c]);
            }
        }
    }

    // Butterfly reduction across lanes: every lane ends with the full sums.
    #pragma unroll
    for (int s = 16; s > 0; s >>= 1) {
        #pragma unroll
        for (int t = 0; t < TGT_PER_WARP; t++)
            #pragma unroll
            for (int c = 0; c < CIN; c++)
                acc[t][c] += __shfl_xor_sync(0xFFFFFFFFu, acc[t][c], s);
    }

    // Fused projection: lane = output channel (COUT == 32).
    #pragma unroll
    for (int t = 0; t < TGT_PER_WARP; t++) {
        float o = b_s[lane];
        #pragma unroll
        for (int c = 0; c < CIN; c++)
            o = fmaf(acc[t][c], W_s[c * COUT + lane], o);
        out[(size_t)(b * NOUT + o0 + t) * COUT + lane] = o;
    }
}

extern "C" void kernel_launch(void* const* d_in, const int* in_sizes, int n_in,
                              void* d_out, int out_size) {
    const float* r     = (const float*)d_in[0];
    const float* xc    = (const float*)d_in[1];
    // d_in[2] = y_context — unused by the reference computation.
    const float* xt    = (const float*)d_in[3];
    const float* sigma = (const float*)d_in[4];
    const float* W     = (const float*)d_in[5];
    const float* bias  = (const float*)d_in[6];
    float* out = (float*)d_out;

    (void)in_sizes; (void)n_in; (void)out_size;

    const int smem_bytes = (CIN * NG + CIN * COUT + COUT) * (int)sizeof(float);
    cudaFuncSetAttribute(conv_decoder_kernel,
                         cudaFuncAttributeMaxDynamicSharedMemorySize, smem_bytes);

    prep_kernel<<<1, TPB>>>(xc, xt, sigma);
    dim3 grid(NOUT / TGT_PER_BLOCK, NB);   // (32, 4) = 128 blocks
    conv_decoder_kernel<<<grid, TPB, smem_bytes>>>(r, xt, W, bias, out);
}